// round 17
// baseline (speedup 1.0000x reference)
#include <cuda_runtime.h>

// CalibrationLayer R17: instruction-diet streamer — contiguous per-CTA tile
// chunks, power-of-2 FIFO with constant-folded slots, split main/epilogue.
//
//  k1 build_pack (unchanged): ri staged in shared; thread-per-bucket binary
//     search in shared; rec(b) = (round(ylo*65535)<<16)|(qy(b+1)-qy(b)).
//  k2 calib_main: 32KB table + 4 x 8KB stages. Each CTA owns a CONTIGUOUS
//     run of tiles; steady loop is #pragma unroll 4 so slot = k&3 and all
//     stage/global offsets are immediates (R16 spent ~55k instr/SM, over half
//     on 64-bit address & FIFO bookkeeping).
// Accuracy: chord dev ~1.6e-5 + quant 8e-6 abs << 1e-3; fb-clamp exact ends.

#define KBUCK   8192
#define QS      65535.0f
#define QINV    (1.0f / 65535.0f)
#define RMAX    4096

#define BUILD_THREADS 512

#define MAIN_THREADS 512
#define MAIN_CTAS    3
#define MAIN_GRID    (148 * MAIN_CTAS)
#define NSTAGE  4
#define ADEPTH  3
#define SMEM_BYTES (KBUCK * 4 + NSTAGE * MAIN_THREADS * 16)   // 64KB

__device__ unsigned int g_tab[KBUCK];

// ---- kernel 1: build + pack, binary search in shared ----
__global__ __launch_bounds__(BUILD_THREADS)
void build_pack(const float* __restrict__ ri,
                const float* __restrict__ ro, int R) {
    __shared__ float sri[RMAX];
    const int rcap = (R < RMAX) ? R : RMAX;
    for (int i = threadIdx.x; i < rcap; i += BUILD_THREADS)
        sri[i] = ri[i];
    __syncthreads();

    const float lo = sri[0];
    const float hi = sri[R - 1];
    const float w  = (hi - lo) / (float)KBUCK;

    auto edge_val = [&](int e) -> float {
        float ex = fmaf((float)e, w, lo);
        int a = 0, b = R - 1;
        while (b - a > 1) {
            int m = (a + b) >> 1;
            if (sri[m] <= ex) a = m; else b = m;
        }
        float xt = sri[a], xp = sri[a + 1];
        float yt = __ldg(ro + a), yp = __ldg(ro + a + 1);
        return yt + (yp - yt) * __fdividef(ex - xt, xp - xt);
    };

    int bk = blockIdx.x * BUILD_THREADS + threadIdx.x;
    if (bk < KBUCK) {
        float yl = edge_val(bk);
        float yh = edge_val(bk + 1);
        int ql = min(max(__float2int_rn(yl * QS), 0), 65535);
        int qh = min(max(__float2int_rn(yh * QS), 0), 65535);
        g_tab[bk] = ((unsigned int)ql << 16) | (unsigned int)(qh - ql);
    }
}

// ---- cp.async helpers ----
__device__ __forceinline__ void cp_async16(unsigned int saddr, const void* gptr) {
    asm volatile("cp.async.cg.shared.global [%0], [%1], 16;"
                 :: "r"(saddr), "l"(gptr));
}
__device__ __forceinline__ void cp_commit() {
    asm volatile("cp.async.commit_group;");
}
#define CP_WAIT_OLDEST() asm volatile("cp.async.wait_group 2;")

// ---- kernel 2: streamer ----
extern __shared__ unsigned char smem_raw[];

__global__ __launch_bounds__(MAIN_THREADS, MAIN_CTAS)
void calib_main(const float* __restrict__ x,
                const float* __restrict__ ri,
                float* __restrict__ out,
                int n, int R) {
    unsigned int* tb = (unsigned int*)smem_raw;
    float4* stage = (float4*)(smem_raw + KBUCK * 4);

    // cooperative table load (coalesced, L2-hot)
    {
        const uint4* __restrict__ src = (const uint4*)g_tab;
        uint4* __restrict__ dst = (uint4*)tb;
        #pragma unroll
        for (int k = 0; k < KBUCK / 4 / MAIN_THREADS; ++k)
            dst[k * MAIN_THREADS + threadIdx.x] = src[k * MAIN_THREADS + threadIdx.x];
    }
    __syncthreads();

    const float lo   = __ldg(&ri[0]);
    const float hi   = __ldg(&ri[R - 1]);
    const float invw = (float)KBUCK / (hi - lo);
    const float nglo = -lo * invw;
    const float fK   = (float)KBUCK;

    auto eval = [&](float xv) -> float {
        float fb = fmaf(xv, invw, nglo);
        fb = fminf(fmaxf(fb, 0.0f), fK);
        int b = (int)fb;
        b = min(b, KBUCK - 1);
        unsigned int rec = tb[b];                         // LDS.32
        float frac = fb - (float)b;
        float qy = (float)(unsigned short)(rec >> 16);    // I2F.U16.H1
        float qd = (float)(unsigned short)rec;            // I2F.U16.H0
        return fmaf(qd, frac, qy) * QINV;
    };

    const int tid    = (int)threadIdx.x;
    const int n4     = n >> 2;
    const int ntiles = n4 / MAIN_THREADS;

    // contiguous balanced chunk: this CTA owns tiles [start, start+T)
    const int q = ntiles / MAIN_GRID;
    const int r = ntiles % MAIN_GRID;
    const int bid = (int)blockIdx.x;
    const int T     = q + (bid < r);
    const int start = bid * q + min(bid, r);

    const float4* __restrict__ xg =
        (const float4*)x + (size_t)start * MAIN_THREADS + tid;
    float4* __restrict__ og =
        (float4*)out + (size_t)start * MAIN_THREADS + tid;

    unsigned int slot0 = (unsigned int)__cvta_generic_to_shared(stage + tid);
    const unsigned int sstride = MAIN_THREADS * 16;

    // prologue: ADEPTH groups (empty commits keep counts aligned)
    #pragma unroll
    for (int j = 0; j < ADEPTH; ++j) {
        if (j < T)
            cp_async16(slot0 + (unsigned)j * sstride, xg + (size_t)j * MAIN_THREADS);
        cp_commit();
    }

    int k = 0;
    const int Tmain = T - ADEPTH;
    // steady state: no issue predicate; slot = k&3 constant-folds under unroll
    #pragma unroll 4
    for (; k < Tmain; ++k) {
        CP_WAIT_OLDEST();
        float4 v = stage[(k & 3) * MAIN_THREADS + tid];
        float4 o;
        o.x = eval(v.x); o.y = eval(v.y); o.z = eval(v.z); o.w = eval(v.w);
        __stcs(og + (size_t)k * MAIN_THREADS, o);
        cp_async16(slot0 + (unsigned)((k + ADEPTH) & 3) * sstride,
                   xg + (size_t)(k + ADEPTH) * MAIN_THREADS);
        cp_commit();
    }
    // epilogue: drain last ADEPTH tiles
    #pragma unroll
    for (int e = 0; e < ADEPTH; ++e, ++k) {
        if (k < T) {
            CP_WAIT_OLDEST();
            float4 v = stage[(k & 3) * MAIN_THREADS + tid];
            float4 o;
            o.x = eval(v.x); o.y = eval(v.y); o.z = eval(v.z); o.w = eval(v.w);
            __stcs(og + (size_t)k * MAIN_THREADS, o);
        }
        cp_commit();
    }

    // remainder float4s + scalar tail: last block, direct
    if (bid == MAIN_GRID - 1) {
        const float4* __restrict__ x4 = (const float4*)x;
        float4* __restrict__ o4 = (float4*)out;
        for (int i = ntiles * MAIN_THREADS + tid; i < n4; i += MAIN_THREADS) {
            float4 v = __ldg(&x4[i]);
            float4 o;
            o.x = eval(v.x); o.y = eval(v.y); o.z = eval(v.z); o.w = eval(v.w);
            o4[i] = o;
        }
        for (int j = (n4 << 2) + tid; j < n; j += MAIN_THREADS)
            out[j] = eval(__ldg(&x[j]));
    }
}

extern "C" void kernel_launch(void* const* d_in, const int* in_sizes, int n_in,
                              void* d_out, int out_size) {
    const float* x  = (const float*)d_in[0];
    const float* ri = (const float*)d_in[1];
    const float* ro = (const float*)d_in[2];
    float* out      = (float*)d_out;
    const int n = in_sizes[0];
    const int R = in_sizes[1];

    build_pack<<<KBUCK / BUILD_THREADS, BUILD_THREADS>>>(ri, ro, R);
    cudaFuncSetAttribute(calib_main, cudaFuncAttributeMaxDynamicSharedMemorySize,
                         SMEM_BYTES);
    calib_main<<<MAIN_GRID, MAIN_THREADS, SMEM_BYTES>>>(x, ri, out, n, R);
}